// round 1
// baseline (speedup 1.0000x reference)
#include <cuda_runtime.h>

// Problem constants (from reference setup_inputs)
#define B_   4
#define C_   128
#define H_   192
#define W_   192
#define K_   9
#define PAD  4          // (K_/2)*stride
#define NOFF (K_*K_)    // 81

// Tiling
#define TH   8          // output rows per block
#define TW   32         // output cols per block
#define PXT  8          // pixels per thread (along w)
#define NWG  (TW/PXT)   // 4 w-groups
#define NTHREADS (NWG * K_ * TH)   // 288
#define CH   8          // channels per smem stage
#define NSTAGE (C_/CH)  // 16
#define YROWS (TH + 2*PAD)   // 16
#define YCOLS (TW + 2*PAD)   // 40
#define YPITCH 44            // padded: conflict-free across i-rows per quarter-warp

// ---- packed f32x2 helpers ----
__device__ __forceinline__ unsigned long long pack2(float lo, float hi) {
    unsigned long long r;
    asm("mov.b64 %0, {%1, %2};" : "=l"(r) : "f"(lo), "f"(hi));
    return r;
}
__device__ __forceinline__ unsigned long long ffma2u(unsigned long long a,
                                                     unsigned long long b,
                                                     unsigned long long c) {
    unsigned long long d;
    asm("fma.rn.f32x2 %0, %1, %2, %3;" : "=l"(d) : "l"(a), "l"(b), "l"(c));
    return d;
}
__device__ __forceinline__ float2 unpack2(unsigned long long v) {
    float2 r;
    asm("mov.b64 {%0, %1}, %2;" : "=f"(r.x), "=f"(r.y) : "l"(v));
    return r;
}

__global__ void __launch_bounds__(NTHREADS, 2)
corr_kernel(const float* __restrict__ x,
            const float* __restrict__ y,
            float* __restrict__ out) {
    __shared__ float xs[CH][TH][TW];        // 8 KB
    __shared__ float ys[CH][YROWS][YPITCH]; // 22 KB

    const int tid = threadIdx.x;
    const int wg  = tid & 3;          // w-group: 8 pixels each
    const int io  = (tid >> 2) % 9;   // i offset row (0..8) — varies within a warp
    const int hr  = tid / 36;         // output row within tile (0..7)

    const int b  = blockIdx.z;
    const int h0 = blockIdx.y * TH;
    const int w0 = blockIdx.x * TW;

    const float* xb = x + (size_t)b * C_ * (H_ * W_);
    const float* yb = y + (size_t)b * C_ * (H_ * W_);

    // accumulators: acc[j][q] = pixels (2q, 2q+1) for j-offset j, fixed i=io
    unsigned long long acc[K_][4];
#pragma unroll
    for (int j = 0; j < K_; j++)
#pragma unroll
        for (int q = 0; q < 4; q++) acc[j][q] = 0ull;

    for (int s = 0; s < NSTAGE; s++) {
        const int c0 = s * CH;

        // ---- load x tile: CH*8*32 floats as float4, fully coalesced ----
        for (int idx = tid; idx < (CH * TH * TW) / 4; idx += NTHREADS) {
            int c  = idx >> 6;          // 64 float4 per channel
            int r  = (idx >> 3) & 7;
            int c4 = idx & 7;
            float4 v = *(const float4*)(xb + (size_t)(c0 + c) * (H_ * W_)
                                        + (h0 + r) * W_ + w0 + c4 * 4);
            *(float4*)&xs[c][r][c4 * 4] = v;
        }

        // ---- load y halo tile: CH*16*40 scalars, zero-filled OOB ----
        for (int idx = tid; idx < CH * YROWS * YCOLS; idx += NTHREADS) {
            int c   = idx / (YROWS * YCOLS);
            int rem = idx - c * (YROWS * YCOLS);
            int r   = rem / YCOLS;
            int col = rem - r * YCOLS;
            int gh  = h0 + r - PAD;
            int gw  = w0 + col - PAD;
            float v = 0.0f;
            if ((unsigned)gh < (unsigned)H_ && (unsigned)gw < (unsigned)W_)
                v = yb[(size_t)(c0 + c) * (H_ * W_) + gh * W_ + gw];
            ys[c][r][col] = v;
        }
        __syncthreads();

        // ---- compute: per channel, 72 FMAs as 36 f32x2 ----
#pragma unroll
        for (int c = 0; c < CH; c++) {
            // x: 8 pixels -> 4 packed pairs (broadcast across i-threads in warp)
            float4 a0 = *(const float4*)&xs[c][hr][wg * PXT];
            float4 a1 = *(const float4*)&xs[c][hr][wg * PXT + 4];
            unsigned long long xq[4];
            xq[0] = pack2(a0.x, a0.y);
            xq[1] = pack2(a0.z, a0.w);
            xq[2] = pack2(a1.x, a1.y);
            xq[3] = pack2(a1.z, a1.w);

            // y: sliding window of 16 floats from row hr+io
            float yv[16];
#pragma unroll
            for (int t = 0; t < 4; t++) {
                float4 bv = *(const float4*)&ys[c][hr + io][wg * PXT + t * 4];
                yv[t * 4 + 0] = bv.x; yv[t * 4 + 1] = bv.y;
                yv[t * 4 + 2] = bv.z; yv[t * 4 + 3] = bv.w;
            }

            // one packed y-pair live at a time: s2 = 2q + j
#pragma unroll
            for (int s2 = 0; s2 < 15; s2++) {
                unsigned long long yp = pack2(yv[s2], yv[s2 + 1]);
#pragma unroll
                for (int q = 0; q < 4; q++) {
                    int j = s2 - 2 * q;
                    if (j >= 0 && j < K_)
                        acc[j][q] = ffma2u(xq[q], yp, acc[j][q]);
                }
            }
        }
        __syncthreads();
    }

    // ---- epilogue: scale by 1/C and store 8 floats per j-offset ----
    const float inv_c = 1.0f / (float)C_;
#pragma unroll
    for (int j = 0; j < K_; j++) {
        int o = io * K_ + j;
        float* op = out + (((size_t)b * NOFF + o) * H_ + (h0 + hr)) * W_
                    + w0 + wg * PXT;
        float2 v0 = unpack2(acc[j][0]);
        float2 v1 = unpack2(acc[j][1]);
        float2 v2 = unpack2(acc[j][2]);
        float2 v3 = unpack2(acc[j][3]);
        float4 o0 = make_float4(v0.x * inv_c, v0.y * inv_c, v1.x * inv_c, v1.y * inv_c);
        float4 o1 = make_float4(v2.x * inv_c, v2.y * inv_c, v3.x * inv_c, v3.y * inv_c);
        *(float4*)op       = o0;
        *(float4*)(op + 4) = o1;
    }
}

extern "C" void kernel_launch(void* const* d_in, const int* in_sizes, int n_in,
                              void* d_out, int out_size) {
    const float* x = (const float*)d_in[0];
    const float* y = (const float*)d_in[1];
    float* out = (float*)d_out;
    dim3 grid(W_ / TW, H_ / TH, B_);   // 6 x 24 x 4 = 576 blocks
    dim3 block(NTHREADS);              // 288 threads
    corr_kernel<<<grid, block>>>(x, y, out);
}

// round 2
// speedup vs baseline: 1.9169x; 1.9169x over previous
#include <cuda_runtime.h>
#include <cstdint>

// Problem constants
#define B_   4
#define C_   128
#define H_   192
#define W_   192
#define HW_  (H_*W_)
#define K_   9
#define PAD  4
#define NOFF 81

// Tiling
#define TH   8
#define TW   32
#define PXT  8
#define NWG  4
#define NTHREADS 288          // 4 wg * 9 io * 8 rows
#define CH   8
#define NSTAGE 16
#define YROWS 16              // TH + 2*PAD
#define YCOLS_S 48            // stored halo cols, origin w0-8 (float4 aligned, no straddle)
#define YPITCH 52             // 52 mod 32 = 20 -> bank-disjoint rows per phase, float4 aligned
#define XSZ  (CH*TH*TW)       // 2048 floats
#define YSZ  (CH*YROWS*YPITCH)// 6656 floats
#define BUFSZ (XSZ + YSZ)     // 8704 floats
#define SMEM_BYTES (2*BUFSZ*4)// 69632 bytes

// ---- packed f32x2 helpers ----
__device__ __forceinline__ unsigned long long pack2(float lo, float hi) {
    unsigned long long r;
    asm("mov.b64 %0, {%1, %2};" : "=l"(r) : "f"(lo), "f"(hi));
    return r;
}
__device__ __forceinline__ unsigned long long ffma2u(unsigned long long a,
                                                     unsigned long long b,
                                                     unsigned long long c) {
    unsigned long long d;
    asm("fma.rn.f32x2 %0, %1, %2, %3;" : "=l"(d) : "l"(a), "l"(b), "l"(c));
    return d;
}
__device__ __forceinline__ float2 unpack2(unsigned long long v) {
    float2 r;
    asm("mov.b64 {%0, %1}, %2;" : "=f"(r.x), "=f"(r.y) : "l"(v));
    return r;
}

// 16B cp.async with zero-fill when srcsize==0
__device__ __forceinline__ void cp16(uint32_t dst, const void* src, int srcsize) {
    asm volatile("cp.async.cg.shared.global [%0], [%1], 16, %2;"
                 :: "r"(dst), "l"(src), "r"(srcsize));
}
__device__ __forceinline__ void cp_commit() {
    asm volatile("cp.async.commit_group;");
}
template <int N>
__device__ __forceinline__ void cp_wait() {
    asm volatile("cp.async.wait_group %0;" :: "n"(N));
}

__global__ void __launch_bounds__(NTHREADS, 2)
corr_kernel(const float* __restrict__ x,
            const float* __restrict__ y,
            float* __restrict__ out) {
    extern __shared__ float sm[];

    const int tid = threadIdx.x;
    const int wg  = tid & 3;
    const int io  = (tid >> 2) % 9;
    const int hr  = tid / 36;

    const int b  = blockIdx.z;
    const int h0 = blockIdx.y * TH;
    const int w0 = blockIdx.x * TW;

    const float* xb = x + (size_t)b * C_ * HW_;
    const float* yb = y + (size_t)b * C_ * HW_;

    const uint32_t sm_base = (uint32_t)__cvta_generic_to_shared(sm);

    // ---- prefetch one stage into buffer `buf` ----
    auto prefetch = [&](int s, int buf) {
        const int c0 = s * CH;
        const uint32_t xs_base = sm_base + (uint32_t)(buf * BUFSZ) * 4u;
        const uint32_t ys_base = xs_base + (uint32_t)XSZ * 4u;

        // x tile: 512 float4, always in-bounds
        {
            int idx = tid;                       // k = 0
            int c  = idx >> 6;
            int r  = (idx >> 3) & 7;
            int c4 = idx & 7;
            const float* src = xb + (size_t)(c0 + c) * HW_ + (h0 + r) * W_ + w0 + c4 * 4;
            cp16(xs_base + (uint32_t)idx * 16u, src, 16);
            idx = tid + NTHREADS;                // k = 1 (224 threads active)
            if (idx < XSZ / 4) {
                c  = idx >> 6; r = (idx >> 3) & 7; c4 = idx & 7;
                src = xb + (size_t)(c0 + c) * HW_ + (h0 + r) * W_ + w0 + c4 * 4;
                cp16(xs_base + (uint32_t)idx * 16u, src, 16);
            }
        }
        // y halo tile: CH*YROWS*12 = 1536 float4, fully-in or fully-out each
#pragma unroll
        for (int k = 0; k < 6; k++) {
            int idx = tid + k * NTHREADS;
            if (idx < CH * YROWS * 12) {
                int c   = idx / (YROWS * 12);
                int rem = idx - c * (YROWS * 12);
                int r   = rem / 12;
                int q   = rem - r * 12;
                int gh  = h0 + r - PAD;
                int gw  = w0 - 8 + q * 4;
                bool ok = ((unsigned)gh < (unsigned)H_) && ((unsigned)gw < (unsigned)W_);
                const float* src = ok
                    ? yb + (size_t)(c0 + c) * HW_ + gh * W_ + gw
                    : yb;                         // valid dummy address
                uint32_t dst = ys_base +
                    (uint32_t)(c * (YROWS * YPITCH) + r * YPITCH + q * 4) * 4u;
                cp16(dst, src, ok ? 16 : 0);
            }
        }
        cp_commit();
    };

    // accumulators: acc[j][q] = pixel pair (2q,2q+1) for j-offset j, i = io
    unsigned long long acc[K_][4];
#pragma unroll
    for (int j = 0; j < K_; j++)
#pragma unroll
        for (int q = 0; q < 4; q++) acc[j][q] = 0ull;

    prefetch(0, 0);

    for (int s = 0; s < NSTAGE; s++) {
        if (s + 1 < NSTAGE) { prefetch(s + 1, (s + 1) & 1); cp_wait<1>(); }
        else                { cp_wait<0>(); }
        __syncthreads();

        const int buf = s & 1;
        const float* xp = sm + buf * BUFSZ + hr * TW + wg * PXT;
        // compute window starts at stored col (wg*8 + 4)  [origin w0-8, first offset gw = w-4]
        const float* yp = sm + buf * BUFSZ + XSZ + (hr + io) * YPITCH + wg * PXT + 4;

#pragma unroll
        for (int c = 0; c < CH; c++) {
            float4 a0 = *(const float4*)(xp);
            float4 a1 = *(const float4*)(xp + 4);
            unsigned long long xq[4];
            xq[0] = pack2(a0.x, a0.y);
            xq[1] = pack2(a0.z, a0.w);
            xq[2] = pack2(a1.x, a1.y);
            xq[3] = pack2(a1.z, a1.w);

            float yv[16];
#pragma unroll
            for (int t = 0; t < 4; t++) {
                float4 bv = *(const float4*)(yp + t * 4);
                yv[t * 4 + 0] = bv.x; yv[t * 4 + 1] = bv.y;
                yv[t * 4 + 2] = bv.z; yv[t * 4 + 3] = bv.w;
            }

#pragma unroll
            for (int s2 = 0; s2 < 15; s2++) {
                unsigned long long ypk = pack2(yv[s2], yv[s2 + 1]);
#pragma unroll
                for (int q = 0; q < 4; q++) {
                    int j = s2 - 2 * q;
                    if (j >= 0 && j < K_)
                        acc[j][q] = ffma2u(xq[q], ypk, acc[j][q]);
                }
            }
            xp += TH * TW;
            yp += YROWS * YPITCH;
        }
        __syncthreads();   // protect buf before next prefetch overwrites it
    }

    // ---- epilogue ----
    const float inv_c = 1.0f / (float)C_;
#pragma unroll
    for (int j = 0; j < K_; j++) {
        int o = io * K_ + j;
        float* op = out + (((size_t)b * NOFF + o) * H_ + (h0 + hr)) * W_
                    + w0 + wg * PXT;
        float2 v0 = unpack2(acc[j][0]);
        float2 v1 = unpack2(acc[j][1]);
        float2 v2 = unpack2(acc[j][2]);
        float2 v3 = unpack2(acc[j][3]);
        float4 o0 = make_float4(v0.x * inv_c, v0.y * inv_c, v1.x * inv_c, v1.y * inv_c);
        float4 o1 = make_float4(v2.x * inv_c, v2.y * inv_c, v3.x * inv_c, v3.y * inv_c);
        *(float4*)op       = o0;
        *(float4*)(op + 4) = o1;
    }
}

extern "C" void kernel_launch(void* const* d_in, const int* in_sizes, int n_in,
                              void* d_out, int out_size) {
    const float* x = (const float*)d_in[0];
    const float* y = (const float*)d_in[1];
    float* out = (float*)d_out;

    static bool attr_set = false;
    if (!attr_set) {
        cudaFuncSetAttribute(corr_kernel,
                             cudaFuncAttributeMaxDynamicSharedMemorySize,
                             SMEM_BYTES);
        attr_set = true;
    }

    dim3 grid(W_ / TW, H_ / TH, B_);   // 6 x 24 x 4 = 576 blocks
    dim3 block(NTHREADS);
    corr_kernel<<<grid, block, SMEM_BYTES>>>(x, y, out);
}